// round 14
// baseline (speedup 1.0000x reference)
#include <cuda_runtime.h>

#define BATCH 16384
#define CH    30
#define GG    49          // 7*7 cells per image
#define CELLS (BATCH * GG) // 802816
#define TPB   128
#define NBLK  (CELLS / TPB)  // 6272, exact
#define NSLOT 128            // accumulator slots (power of 2)

__device__ double g_sums[NSLOT];        // reset by last block each run -> graph-replay safe
__device__ unsigned int g_count = 0;    // wrapping inc -> auto-reset each run

__global__ void __launch_bounds__(TPB)
yolo_fused_kernel(const float* __restrict__ pred, const float* __restrict__ labels,
                  float* __restrict__ out) {
    int tid = blockIdx.x * TPB + threadIdx.x;
    float contrib;
    {
        int b    = tid / GG;
        int cell = tid - b * GG;
        int m    = cell / 7;      // dim -2 index -> gx
        int n    = cell - m * 7;  // dim -1 index -> gy

        const float* pb = pred   + (size_t)b * (CH * GG) + cell;
        const float* lb = labels + (size_t)b * (CH * GG) + cell;

        float p0 = pb[0*GG], p1 = pb[1*GG], p2 = pb[2*GG], p3 = pb[3*GG], p4 = pb[4*GG];
        float p5 = pb[5*GG], p6 = pb[6*GG], p7 = pb[7*GG], p8 = pb[8*GG], p9 = pb[9*GG];
        float l0 = lb[0*GG], l1 = lb[1*GG], l2 = lb[2*GG], l3 = lb[3*GG], l4 = lb[4*GG];
        float l5 = lb[5*GG], l6 = lb[6*GG], l7 = lb[7*GG], l8 = lb[8*GG];

        float gx = (float)m, gy = (float)n;
        const float inv = 1.0f / 7.0f;

        // box 1 (pred ch 0..3)
        float cx1 = (p0 + gx) * inv, cy1 = (p1 + gy) * inv;
        float a1x1 = cx1 - p2 * 0.5f, a1y1 = cy1 - p3 * 0.5f;
        float a1x2 = cx1 + p2 * 0.5f, a1y2 = cy1 + p3 * 0.5f;
        // box 2 (pred ch 5..8)
        float cx2 = (p5 + gx) * inv, cy2 = (p6 + gy) * inv;
        float a2x1 = cx2 - p7 * 0.5f, a2y1 = cy2 - p8 * 0.5f;
        float a2x2 = cx2 + p7 * 0.5f, a2y2 = cy2 + p8 * 0.5f;
        // gt box (labels ch 0..3)
        float cxg = (l0 + gx) * inv, cyg = (l1 + gy) * inv;
        float bx1 = cxg - l2 * 0.5f, by1 = cyg - l3 * 0.5f;
        float bx2 = cxg + l2 * 0.5f, by2 = cyg + l3 * 0.5f;

        float areaB = (bx2 - bx1) * (by2 - by1);

        // iou1
        float ix1 = fmaxf(a1x1, bx1), iy1 = fmaxf(a1y1, by1);
        float ix2 = fminf(a1x2, bx2), iy2 = fminf(a1y2, by2);
        float inter1 = fmaxf(ix2 - ix1, 0.0f) * fmaxf(iy2 - iy1, 0.0f);
        float areaA1 = (a1x2 - a1x1) * (a1y2 - a1y1);
        float iou1 = (inter1 > 0.0f) ? inter1 / (areaA1 + areaB - inter1) : 0.0f;

        // iou2
        float jx1 = fmaxf(a2x1, bx1), jy1 = fmaxf(a2y1, by1);
        float jx2 = fminf(a2x2, bx2), jy2 = fminf(a2y2, by2);
        float inter2 = fmaxf(jx2 - jx1, 0.0f) * fmaxf(jy2 - jy1, 0.0f);
        float areaA2 = (a2x2 - a2x1) * (a2y2 - a2y1);
        float iou2 = (inter2 > 0.0f) ? inter2 / (areaA2 + areaB - inter2) : 0.0f;

        bool resp1 = iou1 > iou2;
        float obj = (l4 == 1.0f) ? 1.0f : 0.0f;

        float d0 = p0 - l0, d1 = p1 - l1;
        float s2 = sqrtf(p2) - sqrtf(l2), s3 = sqrtf(p3) - sqrtf(l3);
        float coor1 = d0*d0 + d1*d1 + s2*s2 + s3*s3;
        float e0 = p5 - l5, e1 = p6 - l6;
        float t2 = sqrtf(p7) - sqrtf(l7), t3 = sqrtf(p8) - sqrtf(l8);
        float coor2 = e0*e0 + e1*e1 + t2*t2 + t3*t3;
        float coor = resp1 ? coor1 : coor2;

        float d4 = p4 - iou1, d9 = p9 - iou2;
        float q4 = d4 * d4, q9 = d9 * d9;
        float obj_conf   = resp1 ? q4 : q9;
        float noobj_resp = resp1 ? q9 : q4;

        // class loss: ch 10..29
        float cls = 0.0f;
        #pragma unroll
        for (int c = 10; c < 30; c++) {
            float dc = pb[c * GG] - lb[c * GG];
            cls += dc * dc;
        }

        contrib = obj * (5.0f * coor + obj_conf + 0.5f * noobj_resp + cls)
                + (1.0f - obj) * 0.5f * (p4 * p4 + p9 * p9);
    }
    double val = (double)contrib;

    // deterministic block reduction (double)
    #pragma unroll
    for (int o = 16; o > 0; o >>= 1)
        val += __shfl_down_sync(0xffffffffu, val, o);

    __shared__ double sdata[TPB / 32];
    int lane = threadIdx.x & 31;
    int wid  = threadIdx.x >> 5;
    if (lane == 0) sdata[wid] = val;
    __syncthreads();

    if (wid == 0 && lane == 0) {
        double bsum = sdata[0] + sdata[1] + sdata[2] + sdata[3];

        // spread atomics over 128 slots -> 128x less per-address serialization
        atomicAdd(&g_sums[blockIdx.x & (NSLOT - 1)], bsum);

        // acq_rel counter: release orders our add before the inc; the RMW chain
        // means the final inc's acquire syncs with ALL earlier blocks' releases.
        unsigned prev;
        asm volatile("atom.acq_rel.gpu.global.inc.u32 %0, [%1], %2;"
                     : "=r"(prev)
                     : "l"(&g_count), "r"((unsigned)(NBLK - 1))
                     : "memory");

        if (prev == NBLK - 1) {
            // last block (only thread 0 of warp 0 is here): all adds visible.
            // Read all slots with acquire loads in fixed order, emit, reset.
            double s = 0.0;
            #pragma unroll 8
            for (int i = 0; i < NSLOT; i++) {
                double v;
                asm volatile("ld.global.acquire.gpu.f64 %0, [%1];"
                             : "=d"(v) : "l"(&g_sums[i]) : "memory");
                s += v;
            }
            out[0] = (float)(s / 6.0);
            #pragma unroll 8
            for (int i = 0; i < NSLOT; i++)
                asm volatile("st.global.relaxed.gpu.f64 [%0], %1;"
                             :: "l"(&g_sums[i]), "d"(0.0) : "memory");
        }
    }
}

extern "C" void kernel_launch(void* const* d_in, const int* in_sizes, int n_in,
                              void* d_out, int out_size) {
    const float* pred   = (const float*)d_in[0];
    const float* labels = (const float*)d_in[1];
    float* out = (float*)d_out;

    yolo_fused_kernel<<<NBLK, TPB>>>(pred, labels, out);
}

// round 15
// speedup vs baseline: 1.7210x; 1.7210x over previous
#include <cuda_runtime.h>

#define BATCH 16384
#define CH    30
#define GG    49          // 7*7 cells per image
#define CELLS (BATCH * GG) // 802816
#define TPB   128
#define NBLK  (CELLS / TPB)  // 6272, exact

__device__ double g_sum = 0.0;          // reset by last block each run -> graph-replay safe
__device__ unsigned int g_count = 0;    // wrapping inc -> auto-reset each run

__global__ void __launch_bounds__(TPB)
yolo_fused_kernel(const float* __restrict__ pred, const float* __restrict__ labels,
                  float* __restrict__ out) {
    int tid = blockIdx.x * TPB + threadIdx.x;
    float contrib;
    {
        int b    = tid / GG;
        int cell = tid - b * GG;
        int m    = cell / 7;      // dim -2 index -> gx
        int n    = cell - m * 7;  // dim -1 index -> gy

        const float* pb = pred   + (size_t)b * (CH * GG) + cell;
        const float* lb = labels + (size_t)b * (CH * GG) + cell;

        float p0 = pb[0*GG], p1 = pb[1*GG], p2 = pb[2*GG], p3 = pb[3*GG], p4 = pb[4*GG];
        float p5 = pb[5*GG], p6 = pb[6*GG], p7 = pb[7*GG], p8 = pb[8*GG], p9 = pb[9*GG];
        float l0 = lb[0*GG], l1 = lb[1*GG], l2 = lb[2*GG], l3 = lb[3*GG], l4 = lb[4*GG];
        float l5 = lb[5*GG], l6 = lb[6*GG], l7 = lb[7*GG], l8 = lb[8*GG];

        float gx = (float)m, gy = (float)n;
        const float inv = 1.0f / 7.0f;

        // box 1 (pred ch 0..3)
        float cx1 = (p0 + gx) * inv, cy1 = (p1 + gy) * inv;
        float a1x1 = cx1 - p2 * 0.5f, a1y1 = cy1 - p3 * 0.5f;
        float a1x2 = cx1 + p2 * 0.5f, a1y2 = cy1 + p3 * 0.5f;
        // box 2 (pred ch 5..8)
        float cx2 = (p5 + gx) * inv, cy2 = (p6 + gy) * inv;
        float a2x1 = cx2 - p7 * 0.5f, a2y1 = cy2 - p8 * 0.5f;
        float a2x2 = cx2 + p7 * 0.5f, a2y2 = cy2 + p8 * 0.5f;
        // gt box (labels ch 0..3)
        float cxg = (l0 + gx) * inv, cyg = (l1 + gy) * inv;
        float bx1 = cxg - l2 * 0.5f, by1 = cyg - l3 * 0.5f;
        float bx2 = cxg + l2 * 0.5f, by2 = cyg + l3 * 0.5f;

        float areaB = (bx2 - bx1) * (by2 - by1);

        // iou1
        float ix1 = fmaxf(a1x1, bx1), iy1 = fmaxf(a1y1, by1);
        float ix2 = fminf(a1x2, bx2), iy2 = fminf(a1y2, by2);
        float inter1 = fmaxf(ix2 - ix1, 0.0f) * fmaxf(iy2 - iy1, 0.0f);
        float areaA1 = (a1x2 - a1x1) * (a1y2 - a1y1);
        float iou1 = (inter1 > 0.0f) ? inter1 / (areaA1 + areaB - inter1) : 0.0f;

        // iou2
        float jx1 = fmaxf(a2x1, bx1), jy1 = fmaxf(a2y1, by1);
        float jx2 = fminf(a2x2, bx2), jy2 = fminf(a2y2, by2);
        float inter2 = fmaxf(jx2 - jx1, 0.0f) * fmaxf(jy2 - jy1, 0.0f);
        float areaA2 = (a2x2 - a2x1) * (a2y2 - a2y1);
        float iou2 = (inter2 > 0.0f) ? inter2 / (areaA2 + areaB - inter2) : 0.0f;

        bool resp1 = iou1 > iou2;
        float obj = (l4 == 1.0f) ? 1.0f : 0.0f;

        float d0 = p0 - l0, d1 = p1 - l1;
        float s2 = sqrtf(p2) - sqrtf(l2), s3 = sqrtf(p3) - sqrtf(l3);
        float coor1 = d0*d0 + d1*d1 + s2*s2 + s3*s3;
        float e0 = p5 - l5, e1 = p6 - l6;
        float t2 = sqrtf(p7) - sqrtf(l7), t3 = sqrtf(p8) - sqrtf(l8);
        float coor2 = e0*e0 + e1*e1 + t2*t2 + t3*t3;
        float coor = resp1 ? coor1 : coor2;

        float d4 = p4 - iou1, d9 = p9 - iou2;
        float q4 = d4 * d4, q9 = d9 * d9;
        float obj_conf   = resp1 ? q4 : q9;
        float noobj_resp = resp1 ? q9 : q4;

        // class loss: ch 10..29
        float cls = 0.0f;
        #pragma unroll
        for (int c = 10; c < 30; c++) {
            float dc = pb[c * GG] - lb[c * GG];
            cls += dc * dc;
        }

        contrib = obj * (5.0f * coor + obj_conf + 0.5f * noobj_resp + cls)
                + (1.0f - obj) * 0.5f * (p4 * p4 + p9 * p9);
    }
    double val = (double)contrib;

    // deterministic block reduction (double)
    #pragma unroll
    for (int o = 16; o > 0; o >>= 1)
        val += __shfl_down_sync(0xffffffffu, val, o);

    __shared__ double sdata[TPB / 32];
    int lane = threadIdx.x & 31;
    int wid  = threadIdx.x >> 5;
    if (lane == 0) sdata[wid] = val;
    __syncthreads();

    if (wid == 0 && lane == 0) {
        double bsum = sdata[0] + sdata[1] + sdata[2] + sdata[3];

        // one double atomic per block into a single L2 accumulator
        atomicAdd(&g_sum, bsum);

        // acq_rel counter: release orders our add before the inc; the RMW chain
        // means the final inc's acquire syncs with ALL earlier blocks' releases.
        unsigned prev;
        asm volatile("atom.acq_rel.gpu.global.inc.u32 %0, [%1], %2;"
                     : "=r"(prev)
                     : "l"(&g_count), "r"((unsigned)(NBLK - 1))
                     : "memory");

        if (prev == NBLK - 1) {
            // last block: all adds visible. Read, emit, reset for next replay.
            double s;
            asm volatile("ld.global.acquire.gpu.f64 %0, [%1];"
                         : "=d"(s) : "l"(&g_sum) : "memory");
            out[0] = (float)(s / 6.0);
            asm volatile("st.global.relaxed.gpu.f64 [%0], %1;"
                         :: "l"(&g_sum), "d"(0.0) : "memory");
        }
    }
}

extern "C" void kernel_launch(void* const* d_in, const int* in_sizes, int n_in,
                              void* d_out, int out_size) {
    const float* pred   = (const float*)d_in[0];
    const float* labels = (const float*)d_in[1];
    float* out = (float*)d_out;

    yolo_fused_kernel<<<NBLK, TPB>>>(pred, labels, out);
}